// round 1
// baseline (speedup 1.0000x reference)
#include <cuda_runtime.h>
#include <math.h>

#define NN      6000
#define DD      128
#define RR      1000
#define MAXDEG  128
#define MAXRDEG 64
#define NB      12000     /* 2*NN: both branches stacked */
#define MAXN_   0.996f    /* 1 - 4e-3 */

/* ------------------------- static scratch (no allocs) ------------------------- */
__device__ __align__(16) float g_seq[(long)NB*3*DD];       /* [n][l][d] */
__device__ __align__(16) float g_hh0[(long)NB*DD];
__device__ __align__(16) float g_hh1[(long)NB*DD];
__device__ float g_es0[NB], g_ed0[NB], g_es1[NB], g_ed1[NB];
__device__ __align__(16) float g_q [(long)NB*3*2*DD];
__device__ __align__(16) float g_k [(long)NB*3*2*DD];
__device__ __align__(16) float g_v [(long)NB*3*2*DD];
__device__ __align__(16) float g_o [(long)NB*3*2*DD];
__device__ __align__(16) float g_of[(long)NB*3*DD];
__device__ __align__(16) float g_u [(long)NB*DD];
__device__ __align__(16) float g_t [(long)NB*DD];
__device__ __align__(16) float g_y [(long)NB*DD];
__device__ __align__(16) float g_w [(long)NB*DD];
__device__ __align__(16) float g_w2[(long)NB*DD];
__device__ __align__(16) float g_Wt[2*DD*DD];
__device__ int g_adj_cols[(long)NB*MAXDEG];
__device__ int g_adj_deg[NB];
__device__ int g_rel_cols[(long)NB*MAXRDEG];
__device__ int g_rel_deg[NB];

/* ------------------------- block (128-thread) reductions ---------------------- */
__device__ __forceinline__ void red_sum(float* v, int nv, float* sbuf /*>=4*nv*/) {
    int lane = threadIdx.x & 31, w = threadIdx.x >> 5;
    for (int i = 0; i < nv; i++) {
        float x = v[i];
#pragma unroll
        for (int o = 16; o; o >>= 1) x += __shfl_xor_sync(0xffffffffu, x, o);
        if (lane == 0) sbuf[i*4 + w] = x;
    }
    __syncthreads();
    for (int i = 0; i < nv; i++)
        v[i] = sbuf[i*4] + sbuf[i*4+1] + sbuf[i*4+2] + sbuf[i*4+3];
    __syncthreads();
}
__device__ __forceinline__ float red_max(float x, float* sbuf /*>=4*/) {
    int lane = threadIdx.x & 31, w = threadIdx.x >> 5;
#pragma unroll
    for (int o = 16; o; o >>= 1) x = fmaxf(x, __shfl_xor_sync(0xffffffffu, x, o));
    if (lane == 0) sbuf[w] = x;
    __syncthreads();
    x = fmaxf(fmaxf(sbuf[0], sbuf[1]), fmaxf(sbuf[2], sbuf[3]));
    __syncthreads();
    return x;
}

/* ------------------------- CSR builders -------------------------------------- */
__global__ void k_build_adj(const float* __restrict__ a0, const float* __restrict__ a1) {
    int row = blockIdx.x, b = blockIdx.y;
    const float* adj = (b ? a1 : a0) + (long)row * NN;
    __shared__ int cnt;
    if (threadIdx.x == 0) cnt = 0;
    __syncthreads();
    int* mc = g_adj_cols + (long)(b*NN + row) * MAXDEG;
    for (int c = threadIdx.x; c < NN; c += blockDim.x)
        if (adj[c] > 0.f) {
            int p = atomicAdd(&cnt, 1);
            if (p < MAXDEG) mc[p] = c;
        }
    __syncthreads();
    if (threadIdx.x == 0) g_adj_deg[b*NN + row] = min(cnt, MAXDEG);
}
__global__ void k_build_rel(const float* __restrict__ a0, const float* __restrict__ a1) {
    int row = blockIdx.x, b = blockIdx.y;
    const float* adj = (b ? a1 : a0) + (long)row * RR;
    __shared__ int cnt;
    if (threadIdx.x == 0) cnt = 0;
    __syncthreads();
    int* mc = g_rel_cols + (long)(b*NN + row) * MAXRDEG;
    for (int c = threadIdx.x; c < RR; c += blockDim.x)
        if (adj[c] > 0.f) {
            int p = atomicAdd(&cnt, 1);
            if (p < MAXRDEG) mc[p] = c;
        }
    __syncthreads();
    if (threadIdx.x == 0) g_rel_deg[b*NN + row] = min(cnt, MAXRDEG);
}

/* ------------------------- rel aggregator ------------------------------------ */
__global__ void k_relagg(const float* __restrict__ r0, const float* __restrict__ r1,
                         float* __restrict__ out) {
    int n = blockIdx.x, b = n / NN, row = n - b*NN, d = threadIdx.x;
    const float* remb = b ? r1 : r0;
    __shared__ int sc[MAXRDEG];
    int deg = g_rel_deg[n];
    for (int j = d; j < deg; j += 128) sc[j] = g_rel_cols[(long)n*MAXRDEG + j];
    __syncthreads();
    float acc = 0.f;
    for (int j = 0; j < deg; j++) acc += remb[(long)sc[j]*DD + d];
    float val = acc / (float)deg;
    out[(long)b*NN*256 + (long)row*256 + 128 + d] = val;
    out[(long)(2+b)*NN*256 + (long)row*256 + 128 + d] = val;
}

/* ------------------------- seq slot-0 ----------------------------------------- */
__global__ void k_seq0(const float* __restrict__ e0, const float* __restrict__ e1) {
    int n = blockIdx.x, b = n / NN, row = n - b*NN, d = threadIdx.x;
    g_seq[(long)n*3*DD + d] = (b ? e1 : e0)[(long)row*DD + d];
}

/* ------------------------- generic SGEMM (BN = 128*gridDim.x) ------------------ */
__global__ __launch_bounds__(256, 2)
void k_gemm(const float* __restrict__ A, int lda,
            const float* __restrict__ B, int ldb,
            float* __restrict__ C, int ldc, int M, int K) {
    const int BM = 128, BK = 16;
    __shared__ float As[BK][BM + 4];
    __shared__ float Bs[BK][128 + 4];
    int tid = threadIdx.x;
    int bm = blockIdx.y * BM, bn = blockIdx.x * 128;
    int tx = tid & 15, ty = tid >> 4;
    float acc[8][8];
#pragma unroll
    for (int i = 0; i < 8; i++)
#pragma unroll
        for (int j = 0; j < 8; j++) acc[i][j] = 0.f;

    for (int k0 = 0; k0 < K; k0 += BK) {
#pragma unroll
        for (int i = 0; i < 2; i++) {
            int lin = tid + i*256;
            int r = lin >> 2, c = (lin & 3) << 2;
            float4 av = make_float4(0.f, 0.f, 0.f, 0.f);
            if (bm + r < M) av = *(const float4*)(A + (long)(bm+r)*lda + k0 + c);
            As[c  ][r] = av.x; As[c+1][r] = av.y; As[c+2][r] = av.z; As[c+3][r] = av.w;
        }
#pragma unroll
        for (int i = 0; i < 2; i++) {
            int lin = tid + i*256;
            int r = lin >> 5, c = (lin & 31) << 2;
            float4 bv = *(const float4*)(B + (long)(k0+r)*ldb + bn + c);
            *(float4*)&Bs[r][c] = bv;
        }
        __syncthreads();
#pragma unroll
        for (int kk = 0; kk < BK; kk++) {
            float a[8], bb[8];
            *(float4*)&a[0]  = *(const float4*)&As[kk][ty*8];
            *(float4*)&a[4]  = *(const float4*)&As[kk][ty*8 + 4];
            *(float4*)&bb[0] = *(const float4*)&Bs[kk][tx*8];
            *(float4*)&bb[4] = *(const float4*)&Bs[kk][tx*8 + 4];
#pragma unroll
            for (int i = 0; i < 8; i++)
#pragma unroll
                for (int j = 0; j < 8; j++) acc[i][j] += a[i] * bb[j];
        }
        __syncthreads();
    }
#pragma unroll
    for (int i = 0; i < 8; i++) {
        int r = bm + ty*8 + i;
        if (r < M) {
#pragma unroll
            for (int j = 0; j < 8; j += 4) {
                float4 cv = make_float4(acc[i][j], acc[i][j+1], acc[i][j+2], acc[i][j+3]);
                *(float4*)(C + (long)r*ldc + bn + tx*8 + j) = cv;
            }
        }
    }
}

/* ------------------------- GAT: es/ed dots ------------------------------------ */
__global__ void k_esed(const float* __restrict__ asrc, const float* __restrict__ adst) {
    int n = blockIdx.x, d = threadIdx.x;
    __shared__ float sbuf[16];
    float h0 = g_hh0[(long)n*DD + d], h1 = g_hh1[(long)n*DD + d];
    float v[4] = { h0*asrc[d], h0*adst[d], h1*asrc[DD + d], h1*adst[DD + d] };
    red_sum(v, 4, sbuf);
    if (d == 0) { g_es0[n] = v[0]; g_ed0[n] = v[1]; g_es1[n] = v[2]; g_ed1[n] = v[3]; }
}

/* ------------------------- GAT: masked softmax aggregation -------------------- */
__global__ void k_gat_agg(int lslot) {
    int n = blockIdx.x, b = n / NN, d = threadIdx.x;
    __shared__ int   sc[MAXDEG];
    __shared__ float sw[MAXDEG];
    __shared__ float sbuf[16];
    int deg = g_adj_deg[n];
    for (int j = d; j < deg; j += 128) sc[j] = g_adj_cols[(long)n*MAXDEG + j];
    __syncthreads();
    float acc[2];
#pragma unroll
    for (int h = 0; h < 2; h++) {
        const float* es = h ? g_es1 : g_es0;
        const float* ed = h ? g_ed1 : g_ed0;
        const float* hh = h ? g_hh1 : g_hh0;
        float esn = es[n];
        float ej = 0.f, e = -1e30f;
        if (d < deg) {
            float t = esn + ed[b*NN + sc[d]];
            ej = (t > 0.f) ? t : 0.2f * t;
            e = ej;
        }
        float m = red_max(e, sbuf);
        float p = (d < deg) ? expf(ej - m) : 0.f;
        float s[1] = { p };
        red_sum(s, 1, sbuf);
        if (d < deg) sw[d] = p / s[0];
        __syncthreads();
        float a = 0.f;
        for (int j = 0; j < deg; j++)
            a += sw[j] * hh[(long)(b*NN + sc[j])*DD + d];
        acc[h] = a;
        __syncthreads();
    }
    float mv = 0.5f * (acc[0] + acc[1]);
    float ev = (mv > 0.f) ? mv : expm1f(mv);                 /* elu */
    float ss[1] = { ev * ev };
    red_sum(ss, 1, sbuf);
    float nrm = fmaxf(sqrtf(ss[0]), 1e-12f);                 /* F.normalize */
    g_seq[((long)n*3 + lslot)*DD + d] = ev / nrm;
}

/* ------------------------- MHA: per-node 3x3 attention ------------------------ */
__global__ void k_mha_attn() {
    int n = blockIdx.x, d = threadIdx.x;
    __shared__ float sq[3][256], sk[3][256], sv[3][256];
    __shared__ float sbuf[16];
    __shared__ float ssc[2][3][3];
    for (int l = 0; l < 3; l++) {
        long base = ((long)n*3 + l) * 256;
        sq[l][d] = g_q[base + d];       sq[l][d+128] = g_q[base + d + 128];
        sk[l][d] = g_k[base + d];       sk[l][d+128] = g_k[base + d + 128];
        sv[l][d] = g_v[base + d];       sv[l][d+128] = g_v[base + d + 128];
    }
    __syncthreads();
    for (int h = 0; h < 2; h++)
        for (int l = 0; l < 3; l++)
            for (int m = 0; m < 3; m++) {
                float s[1] = { sq[l][h*128 + d] * sk[m][h*128 + d] };
                red_sum(s, 1, sbuf);
                if (d == 0) ssc[h][l][m] = s[0] * 0.08838834764831845f; /* 1/sqrt(128) */
            }
    __syncthreads();
    for (int h = 0; h < 2; h++)
        for (int l = 0; l < 3; l++) {
            float a0 = ssc[h][l][0], a1 = ssc[h][l][1], a2 = ssc[h][l][2];
            float m = fmaxf(a0, fmaxf(a1, a2));
            float e0 = expf(a0 - m), e1 = expf(a1 - m), e2 = expf(a2 - m);
            float inv = 1.f / (e0 + e1 + e2);
            float o = (e0*sv[0][h*128+d] + e1*sv[1][h*128+d] + e2*sv[2][h*128+d]) * inv;
            g_o[((long)n*3 + l)*256 + h*128 + d] = o;
        }
}

/* ------------------------- MHA: residual + LN + mean -------------------------- */
__global__ void k_ln(const float* __restrict__ g, const float* __restrict__ bb,
                     float* __restrict__ out) {
    int n = blockIdx.x, b = n / NN, row = n - b*NN, d = threadIdx.x;
    __shared__ float sbuf[16];
    float acc = 0.f;
    for (int l = 0; l < 3; l++) {
        float v = g_of[((long)n*3 + l)*DD + d] + g_seq[((long)n*3 + l)*DD + d];
        float r[2] = { v, v*v };
        red_sum(r, 2, sbuf);
        float mu  = r[0] * (1.f/128.f);
        float var = r[1] * (1.f/128.f) - mu*mu;
        acc += g[d] * (v - mu) * rsqrtf(var + 1e-6f) + bb[d];
    }
    out[(long)b*NN*256 + (long)row*256 + d] = acc * (1.f/3.f);
}

/* ------------------------- HGC pieces ----------------------------------------- */
__global__ void k_u0(const float* __restrict__ e0, const float* __restrict__ e1) {
    int n = blockIdx.x, b = n / NN, row = n - b*NN, d = threadIdx.x;
    __shared__ float sbuf[16];
    float x = (b ? e1 : e0)[(long)row*DD + d];
    float s[1] = { x*x };
    red_sum(s, 1, sbuf);
    float n0 = fmaxf(sqrtf(s[0]), 1e-15f);
    float ne = tanhf(n0);
    float pe = (ne > MAXN_) ? MAXN_/ne : 1.f;
    float np = fmaxf(ne*pe, 1e-15f);
    float c  = atanhf(fminf(np, 1.f - 1e-7f)) / np * (ne / n0) * pe;
    g_u[(long)n*DD + d] = c * x;
}

__global__ void k_transW(const float* __restrict__ W) {
    int j = blockIdx.y, dd = blockIdx.x, e = threadIdx.x;
    g_Wt[j*DD*DD + dd*DD + e] = W[j*DD*DD + e*DD + dd];
}

/* t -> y = logmap0(proj(mobius_add(proj(expmap0(t)), proj(expmap0(b))))) */
__global__ void k_hgc_bias(const float* __restrict__ T, const float* __restrict__ bvec,
                           float* __restrict__ Y) {
    int n = blockIdx.x, d = threadIdx.x;
    __shared__ float sbuf[16];
    float tv = T[(long)n*DD + d], bv = bvec[d];
    float s[3] = { tv*tv, bv*bv, tv*bv };
    red_sum(s, 3, sbuf);
    float nt = fmaxf(sqrtf(s[0]), 1e-15f);
    float et = tanhf(nt);
    float pt = (et > MAXN_) ? MAXN_/et : 1.f;
    float cm = (et/nt) * pt;                 /* mv = cm * t */
    float x2 = (et*pt) * (et*pt);
    float nb = fmaxf(sqrtf(s[1]), 1e-15f);
    float eb = tanhf(nb);
    float pb = (eb > MAXN_) ? MAXN_/eb : 1.f;
    float cb = (eb/nb) * pb;                 /* hb = cb * b */
    float y2 = (eb*pb) * (eb*pb);
    float xy = cm * cb * s[2];
    float den = fmaxf(1.f + 2.f*xy + x2*y2, 1e-15f);
    float r = ((1.f + 2.f*xy + y2) * (cm*tv) + (1.f - x2) * (cb*bv)) / den;
    float s2[1] = { r*r };
    red_sum(s2, 1, sbuf);
    float nr = fmaxf(sqrtf(s2[0]), 1e-15f);
    float pr = (nr > MAXN_) ? MAXN_/nr : 1.f;
    float np = fmaxf(nr*pr, 1e-15f);
    float c2 = atanhf(fminf(np, 1.f - 1e-7f)) / np * pr;
    Y[(long)n*DD + d] = c2 * r;
}

/* SpMM + expmap0/proj + relu-in-tangent + expmap0/proj, then emit logmap0(h) */
__global__ void k_hgc_agg(const float* __restrict__ Y, float* __restrict__ W) {
    int n = blockIdx.x, b = n / NN, d = threadIdx.x;
    __shared__ int sc[MAXDEG];
    __shared__ float sbuf[16];
    int deg = g_adj_deg[n];
    for (int j = d; j < deg; j += 128) sc[j] = g_adj_cols[(long)n*MAXDEG + j];
    __syncthreads();
    float acc = 0.f;
    for (int j = 0; j < deg; j++) acc += Y[(long)(b*NN + sc[j])*DD + d];
    float z = acc / (float)deg;
    float rz = fmaxf(z, 0.f);
    float s[2] = { z*z, rz*rz };
    red_sum(s, 2, sbuf);
    float nz = fmaxf(sqrtf(s[0]), 1e-15f);
    float e1 = tanhf(nz);
    float p1 = (e1 > MAXN_) ? MAXN_/e1 : 1.f;
    float cH = (e1/nz) * p1;                       /* hagg = cH * z */
    float nH = fmaxf(e1*p1, 1e-15f);
    float cT = atanhf(fminf(nH, 1.f - 1e-7f)) / nH * cH;   /* t2 = cT * relu(z) */
    float nt2 = fmaxf(cT * sqrtf(s[1]), 1e-15f);
    float e2 = tanhf(nt2);
    float p2 = (e2 > MAXN_) ? MAXN_/e2 : 1.f;
    float hcoef = (e2/nt2) * p2 * cT;              /* hnext = hcoef * relu(z) */
    float nH2 = fmaxf(e2*p2, 1e-15f);
    float c2 = atanhf(fminf(nH2, 1.f - 1e-7f)) / nH2;
    W[(long)n*DD + d] = c2 * hcoef * rz;           /* = logmap0(hnext) */
}

__global__ void k_hs(const float* __restrict__ e0, const float* __restrict__ e1,
                     float* __restrict__ out) {
    int n = blockIdx.x, b = n / NN, row = n - b*NN, d = threadIdx.x;
    const float* e = b ? e1 : e0;
    out[(long)(2+b)*NN*256 + (long)row*256 + d] = e[(long)row*DD + d] + g_w2[(long)n*DD + d];
}

/* ------------------------- host driver ----------------------------------------- */
extern "C" void kernel_launch(void* const* d_in, const int* in_sizes, int n_in,
                              void* d_out, int out_size) {
    const float* ent_sr    = (const float*)d_in[0];
    const float* ent_tg    = (const float*)d_in[1];
    const float* rel_sr    = (const float*)d_in[2];
    const float* rel_tg    = (const float*)d_in[3];
    const float* adj_sr    = (const float*)d_in[4];
    const float* adj_tg    = (const float*)d_in[5];
    const float* rel_adj_sr= (const float*)d_in[6];
    const float* rel_adj_tg= (const float*)d_in[7];
    const float* gat_W     = (const float*)d_in[8];
    const float* gat_a_src = (const float*)d_in[9];
    const float* gat_a_dst = (const float*)d_in[10];
    const float* Wq        = (const float*)d_in[11];
    const float* Wk        = (const float*)d_in[12];
    const float* Wv        = (const float*)d_in[13];
    const float* Wfc       = (const float*)d_in[14];
    const float* ln_g      = (const float*)d_in[15];
    const float* ln_b      = (const float*)d_in[16];
    const float* hgc_W     = (const float*)d_in[17];
    const float* hgc_b     = (const float*)d_in[18];
    float* out = (float*)d_out;

    float *seq, *hh0, *hh1, *q, *k, *v, *o, *of, *u, *t, *y, *w, *w2, *Wt;
    cudaGetSymbolAddress((void**)&seq, g_seq);
    cudaGetSymbolAddress((void**)&hh0, g_hh0);
    cudaGetSymbolAddress((void**)&hh1, g_hh1);
    cudaGetSymbolAddress((void**)&q,  g_q);
    cudaGetSymbolAddress((void**)&k,  g_k);
    cudaGetSymbolAddress((void**)&v,  g_v);
    cudaGetSymbolAddress((void**)&o,  g_o);
    cudaGetSymbolAddress((void**)&of, g_of);
    cudaGetSymbolAddress((void**)&u,  g_u);
    cudaGetSymbolAddress((void**)&t,  g_t);
    cudaGetSymbolAddress((void**)&y,  g_y);
    cudaGetSymbolAddress((void**)&w,  g_w);
    cudaGetSymbolAddress((void**)&w2, g_w2);
    cudaGetSymbolAddress((void**)&Wt, g_Wt);

    dim3 gM12(1, (12000 + 127) / 128);   /* 94  */
    dim3 gM36_256(2, (36000 + 127) / 128);
    dim3 gM36_128(1, (36000 + 127) / 128);

    /* sparsify */
    k_build_adj<<<dim3(NN, 2), 256>>>(adj_sr, adj_tg);
    k_build_rel<<<dim3(NN, 2), 256>>>(rel_adj_sr, rel_adj_tg);
    k_relagg<<<NB, 128>>>(rel_sr, rel_tg, out);

    /* branch (sr+tg batched): GAT x2 */
    k_seq0<<<NB, 128>>>(ent_sr, ent_tg);
    for (int L = 0; L < 2; L++) {
        const float* A = seq + L * DD;   /* slot L, lda = 3*DD */
        k_gemm<<<gM12, 256>>>(A, 3*DD, gat_W + (L*2+0)*DD*DD, DD, hh0, DD, 12000, DD);
        k_gemm<<<gM12, 256>>>(A, 3*DD, gat_W + (L*2+1)*DD*DD, DD, hh1, DD, 12000, DD);
        k_esed<<<NB, 128>>>(gat_a_src + L*2*DD, gat_a_dst + L*2*DD);
        k_gat_agg<<<NB, 128>>>(L + 1);
    }

    /* MHA */
    k_gemm<<<gM36_256, 256>>>(seq, DD, Wq, 256, q, 256, 36000, DD);
    k_gemm<<<gM36_256, 256>>>(seq, DD, Wk, 256, k, 256, 36000, DD);
    k_gemm<<<gM36_256, 256>>>(seq, DD, Wv, 256, v, 256, 36000, DD);
    k_mha_attn<<<NB, 128>>>();
    k_gemm<<<gM36_128, 256>>>(o, 256, Wfc, DD, of, DD, 36000, 256);
    k_ln<<<NB, 128>>>(ln_g, ln_b, out);

    /* HGC encoder */
    k_u0<<<NB, 128>>>(ent_sr, ent_tg);
    k_transW<<<dim3(DD, 2), DD>>>(hgc_W);
    k_gemm<<<gM12, 256>>>(u, DD, Wt, DD, t, DD, 12000, DD);
    k_hgc_bias<<<NB, 128>>>(t, hgc_b, y);
    k_hgc_agg<<<NB, 128>>>(y, w);
    k_gemm<<<gM12, 256>>>(w, DD, Wt + DD*DD, DD, t, DD, 12000, DD);
    k_hgc_bias<<<NB, 128>>>(t, hgc_b + DD, y);
    k_hgc_agg<<<NB, 128>>>(y, w2);
    k_hs<<<NB, 128>>>(ent_sr, ent_tg, out);
}